// round 1
// baseline (speedup 1.0000x reference)
#include <cuda_runtime.h>
#include <cstdint>

// ============================================================================
// RelativeAttention fused kernel (sm_103a)
//
// out[bn, i=(h,w), j=(x,y)] = dot(q_i, k_j) + QW[bn,i, y-w+31] + QH[bn,i, x-h+31]
//   QW[bn,i,m] = dot(q_i, rel_emb_w[n, m, :]),  QH likewise (n = bn % 8)
//
// Kernel 1: build QW/QH tables (64 x 1024 x 63, padded to 64 cols)
// Kernel 2: batched 1024x1024x64 fp32 GEMM (f32x2 packed FFMA) + gather epilogue
// ============================================================================

#define BNB 64      // b*n batches
#define LQ  1024    // H*W
#define DD  64      // head dim

__device__ float g_qw[(size_t)BNB * LQ * 64];
__device__ float g_qh[(size_t)BNB * LQ * 64];

typedef unsigned long long ull;

__device__ __forceinline__ ull pack2(float lo, float hi) {
    ull r; asm("mov.b64 %0, {%1, %2};" : "=l"(r) : "f"(lo), "f"(hi)); return r;
}
__device__ __forceinline__ void unpack2(ull v, float& lo, float& hi) {
    asm("mov.b64 {%0, %1}, %2;" : "=f"(lo), "=f"(hi) : "l"(v));
}
__device__ __forceinline__ void ffma2(ull& acc, ull a, ull b) {
    asm("fma.rn.f32x2 %0, %1, %2, %0;" : "+l"(acc) : "l"(a), "l"(b));
}

// ----------------------------------------------------------------------------
// Kernel 1: QW/QH tables.
// Grid: (64 bn, 16 row-chunks of 64). 256 threads.
// smem: q_s [64 d][64 i], e_s [64 d][128 m] (m: 0-62 = ew, 63 = 0, 64-126 = eh, 127 = 0)
// Thread tile: 4 i x 8 m (m_thr*4 .. +3  and  +64 .. +67), f32x2 accumulators.
// ----------------------------------------------------------------------------
__global__ __launch_bounds__(256) void rel_tables_kernel(
    const float* __restrict__ q, const float* __restrict__ ew, const float* __restrict__ eh)
{
    __shared__ float q_s[64 * 64];
    __shared__ float e_s[64 * 128];

    const int bn   = blockIdx.x;
    const int ic   = blockIdx.y;
    const int n    = bn & 7;
    const int tid  = threadIdx.x;
    const int lane = tid & 31;
    const int warp = tid >> 5;
    const int i0   = ic * 64;

    const float* Qb = q + ((size_t)bn * LQ + i0) * DD;

    // Stage q (transpose to d-major). Warp w owns d-columns [w*8, w*8+8).
    // smem write addr = d*64 + row, bank = row%32 = lane -> conflict-free.
    #pragma unroll
    for (int rr = 0; rr < 2; rr++) {
        int row = lane + rr * 32;
        #pragma unroll
        for (int g = 0; g < 2; g++) {
            int d0 = warp * 8 + g * 4;
            float4 v = *(const float4*)&Qb[row * DD + d0];
            q_s[(d0 + 0) * 64 + row] = v.x;
            q_s[(d0 + 1) * 64 + row] = v.y;
            q_s[(d0 + 2) * 64 + row] = v.z;
            q_s[(d0 + 3) * 64 + row] = v.w;
        }
    }
    // Stage combined embedding matrix (transpose to d-major).
    #pragma unroll
    for (int part = 0; part < 4; part++) {
        int m = lane + part * 32;
        #pragma unroll
        for (int g = 0; g < 2; g++) {
            int d0 = warp * 8 + g * 4;
            float4 v = make_float4(0.f, 0.f, 0.f, 0.f);
            if (m < 63)                 v = *(const float4*)&ew[((size_t)n * 63 + m) * DD + d0];
            else if (m >= 64 && m < 127) v = *(const float4*)&eh[((size_t)n * 63 + (m - 64)) * DD + d0];
            e_s[(d0 + 0) * 128 + m] = v.x;
            e_s[(d0 + 1) * 128 + m] = v.y;
            e_s[(d0 + 2) * 128 + m] = v.z;
            e_s[(d0 + 3) * 128 + m] = v.w;
        }
    }
    __syncthreads();

    const int m_thr = tid & 15;   // x4 m cols (+ another 4 at +64)
    const int i_thr = tid >> 4;   // x4 i rows

    ull acc[4][4];
    #pragma unroll
    for (int a = 0; a < 4; a++)
        #pragma unroll
        for (int b = 0; b < 4; b++) acc[a][b] = 0ull;

    #pragma unroll 8
    for (int kk = 0; kk < 64; kk++) {
        const float* qs = q_s + kk * 64;
        const float* es = e_s + kk * 128;
        float4 a  = *(const float4*)(qs + i_thr * 4);
        float4 b0 = *(const float4*)(es + m_thr * 4);
        float4 b1 = *(const float4*)(es + m_thr * 4 + 64);
        ull bp[4] = { pack2(b0.x, b0.y), pack2(b0.z, b0.w),
                      pack2(b1.x, b1.y), pack2(b1.z, b1.w) };
        float av[4] = { a.x, a.y, a.z, a.w };
        #pragma unroll
        for (int ii = 0; ii < 4; ii++) {
            ull ab = pack2(av[ii], av[ii]);
            #pragma unroll
            for (int mp = 0; mp < 4; mp++) ffma2(acc[ii][mp], ab, bp[mp]);
        }
    }

    // Store: columns 63 / 127 are dummy slots in the 64-wide tables (never read),
    // so every store is a clean aligned float4 with no guards.
    float* qwb = g_qw + ((size_t)bn * LQ + i0) * 64;
    float* qhb = g_qh + ((size_t)bn * LQ + i0) * 64;
    #pragma unroll
    for (int ii = 0; ii < 4; ii++) {
        int i = i_thr * 4 + ii;
        #pragma unroll
        for (int g = 0; g < 2; g++) {
            float x0, x1, x2, x3;
            unpack2(acc[ii][g * 2 + 0], x0, x1);
            unpack2(acc[ii][g * 2 + 1], x2, x3);
            float4 o = make_float4(x0, x1, x2, x3);
            float* dst = (g == 0) ? qwb : qhb;
            *(float4*)&dst[(size_t)i * 64 + m_thr * 4] = o;
        }
    }
}

// ----------------------------------------------------------------------------
// Kernel 2: batched GEMM + relative-logit epilogue.
// Grid: (8 col-tiles, 8 row-tiles, 64 bn). 256 threads. 64 KB dynamic smem.
// Tile 128x128, full K=64 staged once (no k-loop pipelining needed).
// Warp layout: 2x4 (64 rows x 32 cols per warp); lane layout 8x4;
// thread tile: rows {a+0..3, a+32..35} x cols {b+0..3, b+16..19}.
// Accumulators packed f32x2 along row-pairs (a-pairs free from float4 loads).
// ----------------------------------------------------------------------------
__global__ __launch_bounds__(256, 2) void attn_logits_kernel(
    const float* __restrict__ q, const float* __restrict__ k, float* __restrict__ out)
{
    extern __shared__ float smem[];
    float* As = smem;            // [64 d][128 row]
    float* Bs = smem + 64 * 128; // [64 d][128 col]

    const int bn   = blockIdx.z;
    const int row0 = blockIdx.y * 128;
    const int col0 = blockIdx.x * 128;
    const int tid  = threadIdx.x;
    const int lane = tid & 31;
    const int warp = tid >> 5;

    const float* Qb = q + (size_t)bn * LQ * DD;
    const float* Kb = k + (size_t)bn * LQ * DD;

    // Stage both tiles transposed. Warp w owns d-columns [w*8, w*8+8).
    // smem writes: bank = row%32 = lane -> conflict-free.
    #pragma unroll
    for (int rr = 0; rr < 4; rr++) {
        int row = lane + rr * 32;
        #pragma unroll
        for (int g = 0; g < 2; g++) {
            int d0 = warp * 8 + g * 4;
            float4 va = *(const float4*)&Qb[(size_t)(row0 + row) * DD + d0];
            float4 vb = *(const float4*)&Kb[(size_t)(col0 + row) * DD + d0];
            As[(d0 + 0) * 128 + row] = va.x;
            As[(d0 + 1) * 128 + row] = va.y;
            As[(d0 + 2) * 128 + row] = va.z;
            As[(d0 + 3) * 128 + row] = va.w;
            Bs[(d0 + 0) * 128 + row] = vb.x;
            Bs[(d0 + 1) * 128 + row] = vb.y;
            Bs[(d0 + 2) * 128 + row] = vb.z;
            Bs[(d0 + 3) * 128 + row] = vb.w;
        }
    }
    __syncthreads();

    const int warp_r = warp >> 2;       // 0..1  -> 64-row half
    const int warp_c = warp & 3;        // 0..3  -> 32-col strip
    const int lane_r = lane & 7;        // 8 row groups
    const int lane_c = lane >> 3;       // 4 col groups
    const int a_off  = warp_r * 64 + lane_r * 4;
    const int b_off  = warp_c * 32 + lane_c * 4;

    ull acc[4][8];                      // [row-pair][col]
    #pragma unroll
    for (int a = 0; a < 4; a++)
        #pragma unroll
        for (int c = 0; c < 8; c++) acc[a][c] = 0ull;

    #pragma unroll 8
    for (int kk = 0; kk < 64; kk++) {
        const float* Ar = As + kk * 128;
        const float* Br = Bs + kk * 128;
        float4 a0 = *(const float4*)(Ar + a_off);        // conflict-free (8 x 16B = 128B)
        float4 a1 = *(const float4*)(Ar + a_off + 32);
        float4 b0 = *(const float4*)(Br + b_off);        // 4 addrs, 8-lane broadcast
        float4 b1 = *(const float4*)(Br + b_off + 16);
        ull ap[4] = { pack2(a0.x, a0.y), pack2(a0.z, a0.w),
                      pack2(a1.x, a1.y), pack2(a1.z, a1.w) };
        float bv[8] = { b0.x, b0.y, b0.z, b0.w, b1.x, b1.y, b1.z, b1.w };
        #pragma unroll
        for (int c = 0; c < 8; c++) {
            ull bb = pack2(bv[c], bv[c]);
            #pragma unroll
            for (int rp = 0; rp < 4; rp++) ffma2(acc[rp][c], ap[rp], bb);
        }
    }

    // Epilogue: add QW[i, y-w+31] + QH[i, x-h+31], write float4s.
    float*       outb = out + ((size_t)bn << 20);
    const float* qwb  = g_qw + ((size_t)bn << 16);
    const float* qhb  = g_qh + ((size_t)bn << 16);

    #pragma unroll
    for (int rp = 0; rp < 4; rp++) {
        float lo[8], hi[8];
        #pragma unroll
        for (int c = 0; c < 8; c++) unpack2(acc[rp][c], lo[c], hi[c]);
        int rbase = row0 + a_off + (rp & 1) * 2 + (rp >> 1) * 32;
        #pragma unroll
        for (int half = 0; half < 2; half++) {
            int i = rbase + half;                 // row within batch, 0..1023
            const float* vals = half ? hi : lo;
            int w = i & 31;
            int h = i >> 5;
            const float* qwr = qwb + (size_t)i * 64 + (31 - w);
            const float* qhr = qhb + (size_t)i * 64 + (31 - h);
            #pragma unroll
            for (int g = 0; g < 2; g++) {
                int col = col0 + b_off + g * 16;  // 4-col group, all same x-block
                int x  = col >> 5;
                int y0 = col & 31;
                float hv = __ldg(qhr + x);
                float4 o;
                o.x = vals[g * 4 + 0] + __ldg(qwr + y0 + 0) + hv;
                o.y = vals[g * 4 + 1] + __ldg(qwr + y0 + 1) + hv;
                o.z = vals[g * 4 + 2] + __ldg(qwr + y0 + 2) + hv;
                o.w = vals[g * 4 + 3] + __ldg(qwr + y0 + 3) + hv;
                *(float4*)&outb[(size_t)i * 1024 + col] = o;
            }
        }
    }
}

// ----------------------------------------------------------------------------
extern "C" void kernel_launch(void* const* d_in, const int* in_sizes, int n_in,
                              void* d_out, int out_size)
{
    const float* q  = (const float*)d_in[0];
    const float* k  = (const float*)d_in[1];
    const float* ew = (const float*)d_in[2];
    const float* eh = (const float*)d_in[3];
    float* out = (float*)d_out;

    // Opt-in to 64 KB dynamic smem for the main kernel (idempotent, capture-safe).
    cudaFuncSetAttribute(attn_logits_kernel,
                         cudaFuncAttributeMaxDynamicSharedMemorySize, 64 * 1024);

    rel_tables_kernel<<<dim3(BNB, 16), 256>>>(q, ew, eh);
    attn_logits_kernel<<<dim3(8, 8, BNB), 256, 64 * 1024>>>(q, k, out);
}

// round 5
// speedup vs baseline: 1.1356x; 1.1356x over previous
#include <cuda_runtime.h>
#include <cuda_bf16.h>
#include <cstdint>

// ============================================================================
// RelativeAttention (sm_103, HMMA path — no arch-variant instructions)
//
// out[bn,i=(h,w),j=(x,y)] = dot(q_i,k_j) + QW[bn,i, y-w+31] + QH[bn,i, x-h+31]
//
// K1: QW/QH tables via f32x2 FFMA (exact, verified R1)
// K2: convert q,k -> bf16 hi/lo, K=192 blocked-atom XOR-swizzled images
//     A'' = [hi|hi|lo], B'' = [hi|lo|hi]  -> hi*hi + hi*lo + lo*hi
// K3: mma.sync.m16n8k16 bf16 GEMM, 128x128 tiles, cp.async.bulk triple-
//     buffered B, fused table-gather epilogue
// ============================================================================

#define BNB 64
#define LQ  1024
#define DD  64
#define UNIT_BYTES 49152          // 128 rows x 192 bf16

__device__ float g_qw[(size_t)BNB * LQ * 64];
__device__ float g_qh[(size_t)BNB * LQ * 64];
__device__ __align__(1024) unsigned char g_A[(size_t)512 * UNIT_BYTES];
__device__ __align__(1024) unsigned char g_B[(size_t)512 * UNIT_BYTES];

typedef unsigned long long ull;

// ---------------- helpers ----------------
__device__ __forceinline__ ull pack2(float lo, float hi) {
    ull r; asm("mov.b64 %0, {%1, %2};" : "=l"(r) : "f"(lo), "f"(hi)); return r;
}
__device__ __forceinline__ void unpack2(ull v, float& lo, float& hi) {
    asm("mov.b64 {%0, %1}, %2;" : "=f"(lo), "=f"(hi) : "l"(v));
}
__device__ __forceinline__ void ffma2(ull& acc, ull a, ull b) {
    asm("fma.rn.f32x2 %0, %1, %2, %0;" : "+l"(acc) : "l"(a), "l"(b));
}
__device__ __forceinline__ uint32_t smem_u32(const void* p) {
    uint32_t a;
    asm("{ .reg .u64 t; cvta.to.shared.u64 t, %1; cvt.u32.u64 %0, t; }" : "=r"(a) : "l"(p));
    return a;
}

#define MBAR_INIT(a, c) \
    asm volatile("mbarrier.init.shared.b64 [%0], %1;" :: "r"(a), "r"(c) : "memory")
#define MBAR_EXPECT_TX(a, b) \
    asm volatile("mbarrier.arrive.expect_tx.shared.b64 _, [%0], %1;" :: "r"(a), "r"(b) : "memory")
#define MBAR_WAIT(a, ph) do {                                                   \
    asm volatile("{\n\t.reg .pred P1;\n\t"                                      \
        "WL%=:\n\t"                                                             \
        "mbarrier.try_wait.parity.acquire.cta.shared::cta.b64 P1, [%0], %1, 0x989680;\n\t" \
        "@P1 bra.uni WD%=;\n\t bra.uni WL%=;\n\tWD%=:\n\t}"                      \
        :: "r"(a), "r"(ph) : "memory");                                          \
} while (0)

__device__ __forceinline__ void bulk_g2s(uint32_t dst, const void* src, uint32_t bytes, uint32_t mbar) {
    uint64_t gsrc = (uint64_t)__cvta_generic_to_global(src);
    asm volatile("cp.async.bulk.shared::cta.global.mbarrier::complete_tx::bytes [%0], [%1], %2, [%3];"
                 :: "r"(dst), "l"(gsrc), "r"(bytes), "r"(mbar) : "memory");
}

__device__ __forceinline__ void ldsm4(uint32_t& r0, uint32_t& r1, uint32_t& r2, uint32_t& r3,
                                      uint32_t addr) {
    asm volatile("ldmatrix.sync.aligned.m8n8.x4.shared.b16 {%0,%1,%2,%3}, [%4];"
                 : "=r"(r0), "=r"(r1), "=r"(r2), "=r"(r3) : "r"(addr));
}
__device__ __forceinline__ void mma16816(float* c, const uint32_t* a, const uint32_t* b) {
    asm volatile("mma.sync.aligned.m16n8k16.row.col.f32.bf16.bf16.f32 "
                 "{%0,%1,%2,%3}, {%4,%5,%6,%7}, {%8,%9}, {%0,%1,%2,%3};"
                 : "+f"(c[0]), "+f"(c[1]), "+f"(c[2]), "+f"(c[3])
                 : "r"(a[0]), "r"(a[1]), "r"(a[2]), "r"(a[3]), "r"(b[0]), "r"(b[1]));
}

// blocked-atom XOR-swizzled byte offset inside a 128-row x 192-col bf16 tile
// atom = 8 rows x 64 bf16 (1024B); atom index = (col>>6)*16 + (row>>3)
__device__ __host__ __forceinline__ uint32_t tile_off(int row, int col) {
    uint32_t b = ((uint32_t)(col >> 6) * 16u + (uint32_t)(row >> 3)) * 1024u
               + (uint32_t)(row & 7) * 128u + (uint32_t)(col & 63) * 2u;
    return b ^ ((b >> 3) & 0x70);
}

// ----------------------------------------------------------------------------
// Kernel 1: QW/QH tables (unchanged from R1 - verified exact)
// ----------------------------------------------------------------------------
__global__ __launch_bounds__(256) void rel_tables_kernel(
    const float* __restrict__ q, const float* __restrict__ ew, const float* __restrict__ eh)
{
    __shared__ float q_s[64 * 64];
    __shared__ float e_s[64 * 128];

    const int bn = blockIdx.x, ic = blockIdx.y, n = bn & 7;
    const int tid = threadIdx.x, lane = tid & 31, warp = tid >> 5;
    const int i0 = ic * 64;
    const float* Qb = q + ((size_t)bn * LQ + i0) * DD;

    #pragma unroll
    for (int rr = 0; rr < 2; rr++) {
        int row = lane + rr * 32;
        #pragma unroll
        for (int g = 0; g < 2; g++) {
            int d0 = warp * 8 + g * 4;
            float4 v = *(const float4*)&Qb[row * DD + d0];
            q_s[(d0 + 0) * 64 + row] = v.x; q_s[(d0 + 1) * 64 + row] = v.y;
            q_s[(d0 + 2) * 64 + row] = v.z; q_s[(d0 + 3) * 64 + row] = v.w;
        }
    }
    #pragma unroll
    for (int part = 0; part < 4; part++) {
        int m = lane + part * 32;
        #pragma unroll
        for (int g = 0; g < 2; g++) {
            int d0 = warp * 8 + g * 4;
            float4 v = make_float4(0.f, 0.f, 0.f, 0.f);
            if (m < 63)                  v = *(const float4*)&ew[((size_t)n * 63 + m) * DD + d0];
            else if (m >= 64 && m < 127) v = *(const float4*)&eh[((size_t)n * 63 + (m - 64)) * DD + d0];
            e_s[(d0 + 0) * 128 + m] = v.x; e_s[(d0 + 1) * 128 + m] = v.y;
            e_s[(d0 + 2) * 128 + m] = v.z; e_s[(d0 + 3) * 128 + m] = v.w;
        }
    }
    __syncthreads();

    const int m_thr = tid & 15, i_thr = tid >> 4;
    ull acc[4][4];
    #pragma unroll
    for (int a = 0; a < 4; a++)
        #pragma unroll
        for (int b = 0; b < 4; b++) acc[a][b] = 0ull;

    #pragma unroll 8
    for (int kk = 0; kk < 64; kk++) {
        const float* qs = q_s + kk * 64;
        const float* es = e_s + kk * 128;
        float4 a  = *(const float4*)(qs + i_thr * 4);
        float4 b0 = *(const float4*)(es + m_thr * 4);
        float4 b1 = *(const float4*)(es + m_thr * 4 + 64);
        ull bp[4] = { pack2(b0.x, b0.y), pack2(b0.z, b0.w), pack2(b1.x, b1.y), pack2(b1.z, b1.w) };
        float av[4] = { a.x, a.y, a.z, a.w };
        #pragma unroll
        for (int ii = 0; ii < 4; ii++) {
            ull ab = pack2(av[ii], av[ii]);
            #pragma unroll
            for (int mp = 0; mp < 4; mp++) ffma2(acc[ii][mp], ab, bp[mp]);
        }
    }

    float* qwb = g_qw + ((size_t)bn * LQ + i0) * 64;
    float* qhb = g_qh + ((size_t)bn * LQ + i0) * 64;
    #pragma unroll
    for (int ii = 0; ii < 4; ii++) {
        int i = i_thr * 4 + ii;
        #pragma unroll
        for (int g = 0; g < 2; g++) {
            float x0, x1, x2, x3;
            unpack2(acc[ii][g * 2 + 0], x0, x1);
            unpack2(acc[ii][g * 2 + 1], x2, x3);
            float4 o = make_float4(x0, x1, x2, x3);
            float* dst = (g == 0) ? qwb : qhb;
            *(float4*)&dst[(size_t)i * 64 + m_thr * 4] = o;
        }
    }
}

// ----------------------------------------------------------------------------
// Kernel 2: convert q,k -> bf16 hi/lo blocked-atom swizzled tile images
// grid 1024: blk<512 -> A from q (cols hi|hi|lo); else B from k (hi|lo|hi)
// ----------------------------------------------------------------------------
__device__ __forceinline__ unsigned bfp(float a, float b) {
    __nv_bfloat162 h = __floats2bfloat162_rn(a, b);
    return *reinterpret_cast<unsigned*>(&h);
}

__global__ __launch_bounds__(256) void convert_kernel(
    const float* __restrict__ q, const float* __restrict__ k)
{
    int blk = blockIdx.x;
    bool isA = blk < 512;
    int unit = isA ? blk : blk - 512;
    const float* base = (isA ? q : k) + (size_t)unit * 128 * DD;
    unsigned char* dst = (isA ? g_A : g_B) + (size_t)unit * UNIT_BYTES;
    int tid = threadIdx.x;

    #pragma unroll
    for (int c = 0; c < 4; c++) {
        int chunk = tid + c * 256;          // 0..1023
        int row = chunk >> 3;
        int d0  = (chunk & 7) * 8;
        float4 v0 = *(const float4*)&base[row * DD + d0];
        float4 v1 = *(const float4*)&base[row * DD + d0 + 4];
        float f[8] = { v0.x, v0.y, v0.z, v0.w, v1.x, v1.y, v1.z, v1.w };
        float hi[8], lo[8];
        #pragma unroll
        for (int t = 0; t < 8; t++) {
            __nv_bfloat16 h = __float2bfloat16(f[t]);
            hi[t] = __bfloat162float(h);
            lo[t] = f[t] - hi[t];
        }
        uint4 hpk = make_uint4(bfp(hi[0], hi[1]), bfp(hi[2], hi[3]), bfp(hi[4], hi[5]), bfp(hi[6], hi[7]));
        uint4 lpk = make_uint4(bfp(lo[0], lo[1]), bfp(lo[2], lo[3]), bfp(lo[4], lo[5]), bfp(lo[6], lo[7]));
        // A: [hi | hi | lo], B: [hi | lo | hi]
        *(uint4*)(dst + tile_off(row, d0))       = hpk;
        *(uint4*)(dst + tile_off(row, d0 + 64))  = isA ? hpk : lpk;
        *(uint4*)(dst + tile_off(row, d0 + 128)) = isA ? lpk : hpk;
    }
}

// ----------------------------------------------------------------------------
// Kernel 3: HMMA GEMM + fused relative-logit epilogue
// grid 512 = (bn, row-tile); each CTA loops 8 col-tiles.
// smem: A 48K | B x3 bufs 144K | mbarriers. 256 thr = 8 warps,
// warp tile 64x32 (warp_r = warp>>2, warp_c = warp&3).
// ----------------------------------------------------------------------------
#define AS_OFF   0
#define BS_OFF   49152
#define CTRL_OFF (49152 * 4)     // 196608
#define SMEM_SZ  (196608 + 64)

__global__ __launch_bounds__(256, 1) void attn_hmma_kernel(float* __restrict__ out)
{
    extern __shared__ unsigned char smem[];
    const uint32_t sb = smem_u32(smem);

    const int bn = blockIdx.x >> 3;
    const int rt = blockIdx.x & 7;
    const int row0 = rt * 128;
    const int tid = threadIdx.x, lane = tid & 31, warp = tid >> 5;
    const int warp_r = warp >> 2;     // 0..1 -> 64-row half
    const int warp_c = warp & 3;      // 0..3 -> 32-col strip

    const uint32_t mb0 = sb + CTRL_OFF, mb1 = mb0 + 8, mb2 = mb0 + 16;
    if (tid == 0) { MBAR_INIT(mb0, 1); MBAR_INIT(mb1, 1); MBAR_INIT(mb2, 1); }
    __syncthreads();

    if (tid == 0) {
        MBAR_EXPECT_TX(mb0, 2 * UNIT_BYTES);
        bulk_g2s(sb + AS_OFF, g_A + (size_t)blockIdx.x * UNIT_BYTES, UNIT_BYTES, mb0);
        bulk_g2s(sb + BS_OFF, g_B + (size_t)(bn * 8) * UNIT_BYTES, UNIT_BYTES, mb0);
        MBAR_EXPECT_TX(mb1, UNIT_BYTES);
        bulk_g2s(sb + BS_OFF + UNIT_BYTES, g_B + (size_t)(bn * 8 + 1) * UNIT_BYTES,
                 UNIT_BYTES, mb1);
    }

    // lane decomposition for ldmatrix addressing (8-lane groups -> matrices)
    const int qd = lane >> 3, r8 = lane & 7;
    const uint32_t xorv = (uint32_t)r8 << 4;
    const int mqA = qd & 1, kqA = qd >> 1;    // A: row-half, k-half
    const int jqB = qd >> 1, kqB = qd & 1;    // B: j-half, k-half
    const uint32_t a_lane = sb + AS_OFF + (uint32_t)r8 * 128;

    // epilogue lane mapping
    const int l4 = lane >> 2, l2 = (lane & 3) * 2;
    float*       outb = out + ((size_t)bn << 20);
    const float* qwb  = g_qw + ((size_t)bn << 16);
    const float* qhb  = g_qh + ((size_t)bn << 16);

    for (int ct = 0; ct < 8; ct++) {
        // prefetch B tile ct+2 (its previous readers finished before the
        // __syncthreads that ended iteration ct-1)
        if (tid == 0 && ct < 6) {
            const uint32_t mnext = ((ct + 2) % 3 == 0) ? mb0 : (((ct + 2) % 3 == 1) ? mb1 : mb2);
            MBAR_EXPECT_TX(mnext, UNIT_BYTES);
            bulk_g2s(sb + BS_OFF + ((ct + 2) % 3) * UNIT_BYTES,
                     g_B + (size_t)(bn * 8 + ct + 2) * UNIT_BYTES, UNIT_BYTES, mnext);
        }

        const uint32_t mcur = (ct % 3 == 0) ? mb0 : ((ct % 3 == 1) ? mb1 : mb2);
        MBAR_WAIT(mcur, (ct / 3) & 1);

        const uint32_t b_lane = sb + BS_OFF + (uint32_t)(ct % 3) * UNIT_BYTES
                              + (uint32_t)r8 * 128;

        float acc[4][4][4];               // [mt][n][4]
        #pragma unroll
        for (int mt = 0; mt < 4; mt++)
            #pragma unroll
            for (int n = 0; n < 4; n++)
                #pragma unroll
                for (int e = 0; e < 4; e++) acc[mt][n][e] = 0.f;

        #pragma unroll
        for (int s = 0; s < 12; s++) {
            const int colA = s * 16 + kqA * 8;
            const uint32_t aA = ((uint32_t)(colA >> 6) * 16u) << 10;
            const uint32_t cA = (((uint32_t)(colA & 63)) << 1) ^ xorv;
            uint32_t af[4][4];
            #pragma unroll
            for (int mt = 0; mt < 4; mt++) {
                uint32_t addr = a_lane + aA + cA
                              + (((uint32_t)(warp_r * 8 + mt * 2 + mqA)) << 10);
                ldsm4(af[mt][0], af[mt][1], af[mt][2], af[mt][3], addr);
            }
            const int colB = s * 16 + kqB * 8;
            const uint32_t aB = ((uint32_t)(colB >> 6) * 16u) << 10;
            const uint32_t cB = (((uint32_t)(colB & 63)) << 1) ^ xorv;
            uint32_t bf[2][4];
            #pragma unroll
            for (int ntp = 0; ntp < 2; ntp++) {
                uint32_t addr = b_lane + aB + cB
                              + (((uint32_t)(warp_c * 4 + ntp * 2 + jqB)) << 10);
                ldsm4(bf[ntp][0], bf[ntp][1], bf[ntp][2], bf[ntp][3], addr);
            }
            #pragma unroll
            for (int mt = 0; mt < 4; mt++)
                #pragma unroll
                for (int n = 0; n < 4; n++)
                    mma16816(acc[mt][n], af[mt], &bf[n >> 1][(n & 1) * 2]);
        }

        // fused epilogue: out = acc + qw[i, y-w+31] + qh[i, x-h+31]
        const int xblk = ct * 4 + warp_c;          // x index of this 32-col strip
        #pragma unroll
        for (int mt = 0; mt < 4; mt++) {
            #pragma unroll
            for (int half = 0; half < 2; half++) {
                const int i = row0 + warp_r * 64 + mt * 16 + half * 8 + l4;
                const int w = i & 31, h = i >> 5;
                const float* qwr = qwb + (size_t)i * 64 + (31 - w);
                const float  hv  = __ldg(qhb + (size_t)i * 64 + (31 - h) + xblk);
                float* op = outb + (size_t)i * 1024 + ct * 128 + warp_c * 32 + l2;
                #pragma unroll
                for (int n = 0; n < 4; n++) {
                    const int y = n * 8 + l2;
                    float2 o;
                    o.x = acc[mt][n][half * 2 + 0] + __ldg(qwr + y)     + hv;
                    o.y = acc[mt][n][half * 2 + 1] + __ldg(qwr + y + 1) + hv;
                    *(float2*)(op + n * 8) = o;
                }
            }
        }
        __syncthreads();    // all warps done reading B buffer ct%3
    }
}

// ----------------------------------------------------------------------------
extern "C" void kernel_launch(void* const* d_in, const int* in_sizes, int n_in,
                              void* d_out, int out_size)
{
    const float* q  = (const float*)d_in[0];
    const float* k  = (const float*)d_in[1];
    const float* ew = (const float*)d_in[2];
    const float* eh = (const float*)d_in[3];
    float* out = (float*)d_out;

    cudaFuncSetAttribute(attn_hmma_kernel, cudaFuncAttributeMaxDynamicSharedMemorySize, SMEM_SZ);

    rel_tables_kernel<<<dim3(BNB, 16), 256>>>(q, ew, eh);
    convert_kernel<<<1024, 256>>>(q, k);
    attn_hmma_kernel<<<512, 256, SMEM_SZ>>>(out);
}

// round 7
// speedup vs baseline: 1.7335x; 1.5266x over previous
#include <cuda_runtime.h>
#include <cuda_bf16.h>
#include <cstdint>

// ============================================================================
// RelativeAttention (sm_103, HMMA path)
//
// out[bn,i=(h,w),j=(x,y)] = dot(q_i,k_j) + QW[bn,i, y-w+31] + QH[bn,i, x-h+31]
//
// K1 (convert_b): k -> bf16 hi/lo blocked-atom swizzled B images [hi|lo|hi]
// K2 (attn_hmma): per-CTA:
//   - stage q(fp32), ew, eh in (not yet used) B-buffer smem
//   - compute qw/qh gather WINDOWS in-CTA (32 vals/row each) into padded smem
//   - build A bf16 image [hi|hi|lo] in smem from staged q
//   - 8x 128x128 HMMA col-tiles (K=192), double-buffered B via cp.async.bulk,
//     epilogue adds smem-resident window values, STG.64 out
// ============================================================================

#define BNB 64
#define LQ  1024
#define DD  64
#define UNIT_BYTES 49152          // 128 rows x 192 bf16

__device__ __align__(1024) unsigned char g_B[(size_t)512 * UNIT_BYTES];

typedef unsigned long long ull;

// ---------------- helpers ----------------
__device__ __forceinline__ void ffma2(ull& acc, ull a, ull b) {
    asm("fma.rn.f32x2 %0, %1, %2, %0;" : "+l"(acc) : "l"(a), "l"(b));
}
__device__ __forceinline__ void unpack2(ull v, float& lo, float& hi) {
    asm("mov.b64 {%0, %1}, %2;" : "=f"(lo), "=f"(hi) : "l"(v));
}
__device__ __forceinline__ uint32_t smem_u32(const void* p) {
    uint32_t a;
    asm("{ .reg .u64 t; cvta.to.shared.u64 t, %1; cvt.u32.u64 %0, t; }" : "=r"(a) : "l"(p));
    return a;
}

#define MBAR_INIT(a, c) \
    asm volatile("mbarrier.init.shared.b64 [%0], %1;" :: "r"(a), "r"(c) : "memory")
#define MBAR_EXPECT_TX(a, b) \
    asm volatile("mbarrier.arrive.expect_tx.shared.b64 _, [%0], %1;" :: "r"(a), "r"(b) : "memory")
#define MBAR_WAIT(a, ph) do {                                                   \
    asm volatile("{\n\t.reg .pred P1;\n\t"                                      \
        "WL%=:\n\t"                                                             \
        "mbarrier.try_wait.parity.acquire.cta.shared::cta.b64 P1, [%0], %1, 0x989680;\n\t" \
        "@P1 bra.uni WD%=;\n\t bra.uni WL%=;\n\tWD%=:\n\t}"                      \
        :: "r"(a), "r"(ph) : "memory");                                          \
} while (0)

__device__ __forceinline__ void bulk_g2s(uint32_t dst, const void* src, uint32_t bytes, uint32_t mbar) {
    uint64_t gsrc = (uint64_t)__cvta_generic_to_global(src);
    asm volatile("cp.async.bulk.shared::cta.global.mbarrier::complete_tx::bytes [%0], [%1], %2, [%3];"
                 :: "r"(dst), "l"(gsrc), "r"(bytes), "r"(mbar) : "memory");
}

__device__ __forceinline__ void ldsm4(uint32_t& r0, uint32_t& r1, uint32_t& r2, uint32_t& r3,
                                      uint32_t addr) {
    asm volatile("ldmatrix.sync.aligned.m8n8.x4.shared.b16 {%0,%1,%2,%3}, [%4];"
                 : "=r"(r0), "=r"(r1), "=r"(r2), "=r"(r3) : "r"(addr));
}
__device__ __forceinline__ void mma16816(float* c, const uint32_t* a, const uint32_t* b) {
    asm volatile("mma.sync.aligned.m16n8k16.row.col.f32.bf16.bf16.f32 "
                 "{%0,%1,%2,%3}, {%4,%5,%6,%7}, {%8,%9}, {%0,%1,%2,%3};"
                 : "+f"(c[0]), "+f"(c[1]), "+f"(c[2]), "+f"(c[3])
                 : "r"(a[0]), "r"(a[1]), "r"(a[2]), "r"(a[3]), "r"(b[0]), "r"(b[1]));
}

// blocked-atom XOR-swizzled byte offset inside a 128-row x 192-col bf16 tile
__device__ __host__ __forceinline__ uint32_t tile_off(int row, int col) {
    uint32_t b = ((uint32_t)(col >> 6) * 16u + (uint32_t)(row >> 3)) * 1024u
               + (uint32_t)(row & 7) * 128u + (uint32_t)(col & 63) * 2u;
    return b ^ ((b >> 3) & 0x70);
}

__device__ __forceinline__ unsigned bfp(float a, float b) {
    __nv_bfloat162 h = __floats2bfloat162_rn(a, b);
    return *reinterpret_cast<unsigned*>(&h);
}

// ----------------------------------------------------------------------------
// Kernel 1: convert k -> bf16 hi/lo blocked-atom swizzled B images [hi|lo|hi]
// ----------------------------------------------------------------------------
__global__ __launch_bounds__(256) void convert_b_kernel(const float* __restrict__ k)
{
    int unit = blockIdx.x;
    const float* base = k + (size_t)unit * 128 * DD;
    unsigned char* dst = g_B + (size_t)unit * UNIT_BYTES;
    int tid = threadIdx.x;

    #pragma unroll
    for (int c = 0; c < 4; c++) {
        int chunk = tid + c * 256;          // 0..1023
        int row = chunk >> 3;
        int d0  = (chunk & 7) * 8;
        float4 v0 = *(const float4*)&base[row * DD + d0];
        float4 v1 = *(const float4*)&base[row * DD + d0 + 4];
        float f[8] = { v0.x, v0.y, v0.z, v0.w, v1.x, v1.y, v1.z, v1.w };
        float hi[8], lo[8];
        #pragma unroll
        for (int t = 0; t < 8; t++) {
            __nv_bfloat16 h = __float2bfloat16(f[t]);
            hi[t] = __bfloat162float(h);
            lo[t] = f[t] - hi[t];
        }
        uint4 hpk = make_uint4(bfp(hi[0], hi[1]), bfp(hi[2], hi[3]), bfp(hi[4], hi[5]), bfp(hi[6], hi[7]));
        uint4 lpk = make_uint4(bfp(lo[0], lo[1]), bfp(lo[2], lo[3]), bfp(lo[4], lo[5]), bfp(lo[6], lo[7]));
        *(uint4*)(dst + tile_off(row, d0))       = hpk;   // hi
        *(uint4*)(dst + tile_off(row, d0 + 64))  = lpk;   // lo
        *(uint4*)(dst + tile_off(row, d0 + 128)) = hpk;   // hi
    }
}

// ----------------------------------------------------------------------------
// Kernel 2: fused tables + A-convert + HMMA GEMM + epilogue
// ----------------------------------------------------------------------------
// byte offsets
#define AS_OFF   0
#define BS_OFF   49152                 // two B buffers: 49152*2
#define QW_OFF   147456                // 128 x pitch40 f32 = 20480
#define QH_OFF   167936                // 128 x pitch33 f32 = 16896
#define CTRL_OFF 184832
#define SMEM_SZ  184896
// float-index offsets for staging area (aliases the B buffers, used pre-GEMM)
#define EWF  (BS_OFF / 4)              // ew: 63 rows x pitch66 (float2 stores!)
#define EHF  (EWF + 4160)              // eh: 63 rows x pitch66
#define QF   (EHF + 4160)              // q : 128 rows x pitch68 (fp32)

__global__ __launch_bounds__(256, 1) void attn_hmma_kernel(
    const float* __restrict__ q, const float* __restrict__ ew,
    const float* __restrict__ eh, float* __restrict__ out)
{
    extern __shared__ unsigned char smem[];
    float* smem_f = (float*)smem;
    const uint32_t sb = smem_u32(smem);

    const int bn = blockIdx.x >> 3;
    const int rt = blockIdx.x & 7;
    const int row0 = rt * 128;
    const int n_head = bn & 7;
    const int tid = threadIdx.x, lane = tid & 31, warp = tid >> 5;
    const int warp_r = warp >> 2;     // 0..1 -> 64-row half
    const int warp_c = warp & 3;      // 0..3 -> 32-col strip

    const uint32_t mb0 = sb + CTRL_OFF, mb1 = mb0 + 8;
    if (tid == 0) { MBAR_INIT(mb0, 1); MBAR_INIT(mb1, 1); }

    // ---- stage ew, eh, q(fp32) into the (pre-GEMM) B-buffer region ----
    // ew/eh pitch 66 floats: rows are only 8B-aligned -> use float2 stores.
    {
        const float* ewb = ew + (size_t)n_head * 63 * DD;
        const float* ehb = eh + (size_t)n_head * 63 * DD;
        for (int c = tid; c < 1008; c += 256) {          // 63 rows x 16 float4
            int row = c >> 4, d0 = (c & 15) * 4;
            float4 vw = *(const float4*)&ewb[row * DD + d0];
            float4 vh = *(const float4*)&ehb[row * DD + d0];
            float* dw = &smem_f[EWF + row * 66 + d0];
            float* dh = &smem_f[EHF + row * 66 + d0];
            *(float2*)(dw + 0) = make_float2(vw.x, vw.y);
            *(float2*)(dw + 2) = make_float2(vw.z, vw.w);
            *(float2*)(dh + 0) = make_float2(vh.x, vh.y);
            *(float2*)(dh + 2) = make_float2(vh.z, vh.w);
        }
        const float* qb = q + ((size_t)bn * LQ + row0) * DD;
        #pragma unroll
        for (int it = 0; it < 8; it++) {                 // 128 rows x 16 float4
            int c = tid + it * 256;
            int row = c >> 4, d0 = (c & 15) * 4;
            *(float4*)&smem_f[QF + row * 68 + d0] = *(const float4*)&qb[(size_t)row * DD + d0];
        }
    }
    __syncthreads();

    // ---- build A bf16 image [hi|hi|lo] from staged q ----
    #pragma unroll
    for (int c = 0; c < 4; c++) {
        int chunk = tid + c * 256;
        int row = chunk >> 3;
        int d0  = (chunk & 7) * 8;
        float4 v0 = *(const float4*)&smem_f[QF + row * 68 + d0];
        float4 v1 = *(const float4*)&smem_f[QF + row * 68 + d0 + 4];
        float f[8] = { v0.x, v0.y, v0.z, v0.w, v1.x, v1.y, v1.z, v1.w };
        float hi[8], lo[8];
        #pragma unroll
        for (int t = 0; t < 8; t++) {
            __nv_bfloat16 h = __float2bfloat16(f[t]);
            hi[t] = __bfloat162float(h);
            lo[t] = f[t] - hi[t];
        }
        uint4 hpk = make_uint4(bfp(hi[0], hi[1]), bfp(hi[2], hi[3]), bfp(hi[4], hi[5]), bfp(hi[6], hi[7]));
        uint4 lpk = make_uint4(bfp(lo[0], lo[1]), bfp(lo[2], lo[3]), bfp(lo[4], lo[5]), bfp(lo[6], lo[7]));
        *(uint4*)(smem + AS_OFF + tile_off(row, d0))       = hpk;
        *(uint4*)(smem + AS_OFF + tile_off(row, d0 + 64))  = hpk;
        *(uint4*)(smem + AS_OFF + tile_off(row, d0 + 128)) = lpk;
    }

    // ---- compute qw/qh gather windows (32 vals per row each), fp32 ----
    // task<128: qw row; else qh row. lane = window index y/x (0..31).
    float* qw_s = smem_f + QW_OFF / 4;   // [row][y] pitch 40
    float* qh_s = smem_f + QH_OFF / 4;   // [row][x] pitch 33
    #pragma unroll 1
    for (int pass = 0; pass < 32; pass++) {
        int task = warp * 32 + pass;
        bool isW = task < 128;
        int r = isW ? task : task - 128;
        int shift = isW ? (31 - (r & 31)) : (31 - (rt * 4 + (r >> 5)));
        const float* erow = smem_f + (isW ? EWF : EHF) + (size_t)(shift + lane) * 66;
        const float* qrow = smem_f + QF + (size_t)r * 68;
        ull acc = 0;
        #pragma unroll 8
        for (int kk = 0; kk < 32; kk++) {
            ull qp = *(const ull*)(qrow + 2 * kk);   // broadcast
            ull ep = *(const ull*)(erow + 2 * kk);
            ffma2(acc, qp, ep);
        }
        float vlo, vhi; unpack2(acc, vlo, vhi);
        float v = vlo + vhi;
        if (isW) qw_s[r * 40 + lane] = v;
        else     qh_s[r * 33 + lane] = v;
    }
    __syncthreads();   // staging reads done; A image + tables visible

    // ---- kick off double-buffered B loads ----
    if (tid == 0) {
        MBAR_EXPECT_TX(mb0, UNIT_BYTES);
        bulk_g2s(sb + BS_OFF, g_B + (size_t)(bn * 8) * UNIT_BYTES, UNIT_BYTES, mb0);
        MBAR_EXPECT_TX(mb1, UNIT_BYTES);
        bulk_g2s(sb + BS_OFF + UNIT_BYTES, g_B + (size_t)(bn * 8 + 1) * UNIT_BYTES,
                 UNIT_BYTES, mb1);
    }

    // lane decomposition for ldmatrix addressing
    const int qd = lane >> 3, r8 = lane & 7;
    const uint32_t xorv = (uint32_t)r8 << 4;
    const int mqA = qd & 1, kqA = qd >> 1;    // A: row-half, k-half
    const int jqB = qd >> 1, kqB = qd & 1;    // B: j-half, k-half
    const uint32_t a_lane = sb + AS_OFF + (uint32_t)r8 * 128;

    // epilogue lane mapping
    const int l4 = lane >> 2, l2 = (lane & 3) * 2;
    float* outb = out + ((size_t)bn << 20);

    for (int ct = 0; ct < 8; ct++) {
        // prefetch tile ct+1 into the other buffer (freed by the sync that
        // ended iteration ct-1); tiles 0/1 already in flight
        if (tid == 0 && ct >= 1 && ct < 7) {
            const uint32_t mnext = ((ct + 1) & 1) ? mb1 : mb0;
            MBAR_EXPECT_TX(mnext, UNIT_BYTES);
            bulk_g2s(sb + BS_OFF + ((ct + 1) & 1) * UNIT_BYTES,
                     g_B + (size_t)(bn * 8 + ct + 1) * UNIT_BYTES, UNIT_BYTES, mnext);
        }

        MBAR_WAIT((ct & 1) ? mb1 : mb0, (ct >> 1) & 1);

        const uint32_t b_lane = sb + BS_OFF + (uint32_t)(ct & 1) * UNIT_BYTES
                              + (uint32_t)r8 * 128;

        float acc[4][4][4];
        #pragma unroll
        for (int mt = 0; mt < 4; mt++)
            #pragma unroll
            for (int nn = 0; nn < 4; nn++)
                #pragma unroll
                for (int e = 0; e < 4; e++) acc[mt][nn][e] = 0.f;

        #pragma unroll
        for (int s = 0; s < 12; s++) {
            const int colA = s * 16 + kqA * 8;
            const uint32_t aA = ((uint32_t)(colA >> 6) * 16u) << 10;
            const uint32_t cA = (((uint32_t)(colA & 63)) << 1) ^ xorv;
            uint32_t af[4][4];
            #pragma unroll
            for (int mt = 0; mt < 4; mt++) {
                uint32_t addr = a_lane + aA + cA
                              + (((uint32_t)(warp_r * 8 + mt * 2 + mqA)) << 10);
                ldsm4(af[mt][0], af[mt][1], af[mt][2], af[mt][3], addr);
            }
            const int colB = s * 16 + kqB * 8;
            const uint32_t aB = ((uint32_t)(colB >> 6) * 16u) << 10;
            const uint32_t cB = (((uint32_t)(colB & 63)) << 1) ^ xorv;
            uint32_t bf[2][4];
            #pragma unroll
            for (int ntp = 0; ntp < 2; ntp++) {
                uint32_t addr = b_lane + aB + cB
                              + (((uint32_t)(warp_c * 4 + ntp * 2 + jqB)) << 10);
                ldsm4(bf[ntp][0], bf[ntp][1], bf[ntp][2], bf[ntp][3], addr);
            }
            #pragma unroll
            for (int mt = 0; mt < 4; mt++)
                #pragma unroll
                for (int nn = 0; nn < 4; nn++)
                    mma16816(acc[mt][nn], af[mt], &bf[nn >> 1][(nn & 1) * 2]);
        }

        // epilogue: out = acc + qw_s[r][y] + qh_s[r][x] (all smem, conflict-free)
        const int xq = ct * 4 + warp_c;          // warp-uniform x index
        #pragma unroll
        for (int mt = 0; mt < 4; mt++) {
            #pragma unroll
            for (int half = 0; half < 2; half++) {
                const int r = warp_r * 64 + mt * 16 + half * 8 + l4;   // local row
                const float hv = qh_s[r * 33 + xq];
                float* op = outb + (size_t)(row0 + r) * 1024 + ct * 128 + warp_c * 32 + l2;
                #pragma unroll
                for (int nn = 0; nn < 4; nn++) {
                    float2 wv = *(const float2*)&qw_s[r * 40 + nn * 8 + l2];
                    float2 o;
                    o.x = acc[mt][nn][half * 2 + 0] + wv.x + hv;
                    o.y = acc[mt][nn][half * 2 + 1] + wv.y + hv;
                    *(float2*)(op + nn * 8) = o;
                }
            }
        }
        __syncthreads();    // all warps done with this B buffer
    }
}

// ----------------------------------------------------------------------------
extern "C" void kernel_launch(void* const* d_in, const int* in_sizes, int n_in,
                              void* d_out, int out_size)
{
    const float* q  = (const float*)d_in[0];
    const float* k  = (const float*)d_in[1];
    const float* ew = (const float*)d_in[2];
    const float* eh = (const float*)d_in[3];
    float* out = (float*)d_out;

    cudaFuncSetAttribute(attn_hmma_kernel, cudaFuncAttributeMaxDynamicSharedMemorySize, SMEM_SZ);

    convert_b_kernel<<<512, 256>>>(k);
    attn_hmma_kernel<<<512, 256, SMEM_SZ>>>(q, ew, eh, out);
}

// round 8
// speedup vs baseline: 1.8713x; 1.0795x over previous
#include <cuda_runtime.h>
#include <cuda_bf16.h>
#include <cstdint>

// ============================================================================
// RelativeAttention (sm_103, HMMA path, warp-desynced pipeline)
//
// out[bn,i=(h,w),j=(x,y)] = dot(q_i,k_j) + QW[bn,i, y-w+31] + QH[bn,i, x-h+31]
//
// K1 (convert_b): k -> bf16 hi/lo blocked-atom swizzled B images [hi|lo|hi]
// K2 (attn_hmma): 288 thr = 8 worker warps + 1 producer warp.
//   - in-CTA qw/qh windows + A bf16 image [hi|hi|lo]
//   - 8x 128x128 HMMA col-tiles (K=192), B double-buffered via producer-warp
//     cp.async.bulk; consumed[] mbarriers replace per-tile __syncthreads so
//     worker warps free-run (epilogue overlaps other warps' MMA)
//   - qw window hoisted into registers (ct-invariant)
// ============================================================================

#define BNB 64
#define LQ  1024
#define DD  64
#define UNIT_BYTES 49152          // 128 rows x 192 bf16

__device__ __align__(1024) unsigned char g_B[(size_t)512 * UNIT_BYTES];

typedef unsigned long long ull;

// ---------------- helpers ----------------
__device__ __forceinline__ void ffma2(ull& acc, ull a, ull b) {
    asm("fma.rn.f32x2 %0, %1, %2, %0;" : "+l"(acc) : "l"(a), "l"(b));
}
__device__ __forceinline__ void unpack2(ull v, float& lo, float& hi) {
    asm("mov.b64 {%0, %1}, %2;" : "=f"(lo), "=f"(hi) : "l"(v));
}
__device__ __forceinline__ uint32_t smem_u32(const void* p) {
    uint32_t a;
    asm("{ .reg .u64 t; cvta.to.shared.u64 t, %1; cvt.u32.u64 %0, t; }" : "=r"(a) : "l"(p));
    return a;
}
__device__ __forceinline__ uint32_t elect_one() {
    uint32_t p;
    asm volatile("{ .reg .pred p; elect.sync _|p, 0xFFFFFFFF; selp.b32 %0, 1, 0, p; }" : "=r"(p));
    return p;
}

#define MBAR_INIT(a, c) \
    asm volatile("mbarrier.init.shared.b64 [%0], %1;" :: "r"(a), "r"(c) : "memory")
#define MBAR_EXPECT_TX(a, b) \
    asm volatile("mbarrier.arrive.expect_tx.shared.b64 _, [%0], %1;" :: "r"(a), "r"(b) : "memory")
#define MBAR_ARRIVE(a) \
    asm volatile("mbarrier.arrive.shared.b64 _, [%0];" :: "r"(a) : "memory")
#define MBAR_WAIT(a, ph) do {                                                   \
    asm volatile("{\n\t.reg .pred P1;\n\t"                                      \
        "WL%=:\n\t"                                                             \
        "mbarrier.try_wait.parity.acquire.cta.shared::cta.b64 P1, [%0], %1, 0x989680;\n\t" \
        "@P1 bra.uni WD%=;\n\t bra.uni WL%=;\n\tWD%=:\n\t}"                      \
        :: "r"(a), "r"(ph) : "memory");                                          \
} while (0)

__device__ __forceinline__ void bulk_g2s(uint32_t dst, const void* src, uint32_t bytes, uint32_t mbar) {
    uint64_t gsrc = (uint64_t)__cvta_generic_to_global(src);
    asm volatile("cp.async.bulk.shared::cta.global.mbarrier::complete_tx::bytes [%0], [%1], %2, [%3];"
                 :: "r"(dst), "l"(gsrc), "r"(bytes), "r"(mbar) : "memory");
}

__device__ __forceinline__ void ldsm4(uint32_t& r0, uint32_t& r1, uint32_t& r2, uint32_t& r3,
                                      uint32_t addr) {
    asm volatile("ldmatrix.sync.aligned.m8n8.x4.shared.b16 {%0,%1,%2,%3}, [%4];"
                 : "=r"(r0), "=r"(r1), "=r"(r2), "=r"(r3) : "r"(addr));
}
__device__ __forceinline__ void mma16816(float* c, const uint32_t* a, const uint32_t* b) {
    asm volatile("mma.sync.aligned.m16n8k16.row.col.f32.bf16.bf16.f32 "
                 "{%0,%1,%2,%3}, {%4,%5,%6,%7}, {%8,%9}, {%0,%1,%2,%3};"
                 : "+f"(c[0]), "+f"(c[1]), "+f"(c[2]), "+f"(c[3])
                 : "r"(a[0]), "r"(a[1]), "r"(a[2]), "r"(a[3]), "r"(b[0]), "r"(b[1]));
}

// blocked-atom XOR-swizzled byte offset inside a 128-row x 192-col bf16 tile
__device__ __host__ __forceinline__ uint32_t tile_off(int row, int col) {
    uint32_t b = ((uint32_t)(col >> 6) * 16u + (uint32_t)(row >> 3)) * 1024u
               + (uint32_t)(row & 7) * 128u + (uint32_t)(col & 63) * 2u;
    return b ^ ((b >> 3) & 0x70);
}

__device__ __forceinline__ unsigned bfp(float a, float b) {
    __nv_bfloat162 h = __floats2bfloat162_rn(a, b);
    return *reinterpret_cast<unsigned*>(&h);
}

// ----------------------------------------------------------------------------
// Kernel 1: convert k -> bf16 hi/lo blocked-atom swizzled B images [hi|lo|hi]
// ----------------------------------------------------------------------------
__global__ __launch_bounds__(256) void convert_b_kernel(const float* __restrict__ k)
{
    int unit = blockIdx.x;
    const float* base = k + (size_t)unit * 128 * DD;
    unsigned char* dst = g_B + (size_t)unit * UNIT_BYTES;
    int tid = threadIdx.x;

    #pragma unroll
    for (int c = 0; c < 4; c++) {
        int chunk = tid + c * 256;          // 0..1023
        int row = chunk >> 3;
        int d0  = (chunk & 7) * 8;
        float4 v0 = *(const float4*)&base[row * DD + d0];
        float4 v1 = *(const float4*)&base[row * DD + d0 + 4];
        float f[8] = { v0.x, v0.y, v0.z, v0.w, v1.x, v1.y, v1.z, v1.w };
        float hi[8], lo[8];
        #pragma unroll
        for (int t = 0; t < 8; t++) {
            __nv_bfloat16 h = __float2bfloat16(f[t]);
            hi[t] = __bfloat162float(h);
            lo[t] = f[t] - hi[t];
        }
        uint4 hpk = make_uint4(bfp(hi[0], hi[1]), bfp(hi[2], hi[3]), bfp(hi[4], hi[5]), bfp(hi[6], hi[7]));
        uint4 lpk = make_uint4(bfp(lo[0], lo[1]), bfp(lo[2], lo[3]), bfp(lo[4], lo[5]), bfp(lo[6], lo[7]));
        *(uint4*)(dst + tile_off(row, d0))       = hpk;   // hi
        *(uint4*)(dst + tile_off(row, d0 + 64))  = lpk;   // lo
        *(uint4*)(dst + tile_off(row, d0 + 128)) = hpk;   // hi
    }
}

// ----------------------------------------------------------------------------
// Kernel 2: fused tables + A-convert + HMMA GEMM + epilogue
// ----------------------------------------------------------------------------
// byte offsets
#define AS_OFF   0
#define BS_OFF   49152                 // two B buffers: 49152*2
#define QW_OFF   147456                // 128 x pitch40 f32 = 20480
#define QH_OFF   167936                // 128 x pitch33 f32 = 16896
#define CTRL_OFF 184832
#define SMEM_SZ  184896
// float-index offsets for staging area (aliases the B buffers, used pre-GEMM)
#define EWF  (BS_OFF / 4)              // ew: 63 rows x pitch66 (float2 stores)
#define EHF  (EWF + 4160)              // eh: 63 rows x pitch66
#define QF   (EHF + 4160)              // q : 128 rows x pitch68 (fp32)

__global__ __launch_bounds__(288, 1) void attn_hmma_kernel(
    const float* __restrict__ q, const float* __restrict__ ew,
    const float* __restrict__ eh, float* __restrict__ out)
{
    extern __shared__ unsigned char smem[];
    float* smem_f = (float*)smem;
    const uint32_t sb = smem_u32(smem);

    const int bn = blockIdx.x >> 3;
    const int rt = blockIdx.x & 7;
    const int row0 = rt * 128;
    const int n_head = bn & 7;
    const int tid = threadIdx.x, lane = tid & 31, warp = tid >> 5;
    const int warp_r = warp >> 2;     // workers: 0..1 -> 64-row half
    const int warp_c = warp & 3;      // workers: 0..3 -> 32-col strip

    const uint32_t mb0 = sb + CTRL_OFF,      mb1 = mb0 + 8;   // B-full (count 1)
    const uint32_t mc0 = mb0 + 16,           mc1 = mb0 + 24;  // B-consumed (count 8)
    if (tid == 0) {
        MBAR_INIT(mb0, 1); MBAR_INIT(mb1, 1);
        MBAR_INIT(mc0, 8); MBAR_INIT(mc1, 8);
    }

    // ---- stage ew, eh, q(fp32) into the (pre-GEMM) B-buffer region ----
    if (tid < 256) {
        const float* ewb = ew + (size_t)n_head * 63 * DD;
        const float* ehb = eh + (size_t)n_head * 63 * DD;
        for (int c = tid; c < 1008; c += 256) {          // 63 rows x 16 float4
            int row = c >> 4, d0 = (c & 15) * 4;
            float4 vw = *(const float4*)&ewb[row * DD + d0];
            float4 vh = *(const float4*)&ehb[row * DD + d0];
            float* dw = &smem_f[EWF + row * 66 + d0];
            float* dh = &smem_f[EHF + row * 66 + d0];
            *(float2*)(dw + 0) = make_float2(vw.x, vw.y);
            *(float2*)(dw + 2) = make_float2(vw.z, vw.w);
            *(float2*)(dh + 0) = make_float2(vh.x, vh.y);
            *(float2*)(dh + 2) = make_float2(vh.z, vh.w);
        }
        const float* qb = q + ((size_t)bn * LQ + row0) * DD;
        #pragma unroll
        for (int it = 0; it < 8; it++) {                 // 128 rows x 16 float4
            int c = tid + it * 256;
            int row = c >> 4, d0 = (c & 15) * 4;
            *(float4*)&smem_f[QF + row * 68 + d0] = *(const float4*)&qb[(size_t)row * DD + d0];
        }
    }
    __syncthreads();

    // ---- build A bf16 image [hi|hi|lo] from staged q ----
    if (tid < 256) {
        #pragma unroll
        for (int c = 0; c < 4; c++) {
            int chunk = tid + c * 256;
            int row = chunk >> 3;
            int d0  = (chunk & 7) * 8;
            float4 v0 = *(const float4*)&smem_f[QF + row * 68 + d0];
            float4 v1 = *(const float4*)&smem_f[QF + row * 68 + d0 + 4];
            float f[8] = { v0.x, v0.y, v0.z, v0.w, v1.x, v1.y, v1.z, v1.w };
            float hi[8], lo[8];
            #pragma unroll
            for (int t = 0; t < 8; t++) {
                __nv_bfloat16 h = __float2bfloat16(f[t]);
                hi[t] = __bfloat162float(h);
                lo[t] = f[t] - hi[t];
            }
            uint4 hpk = make_uint4(bfp(hi[0], hi[1]), bfp(hi[2], hi[3]), bfp(hi[4], hi[5]), bfp(hi[6], hi[7]));
            uint4 lpk = make_uint4(bfp(lo[0], lo[1]), bfp(lo[2], lo[3]), bfp(lo[4], lo[5]), bfp(lo[6], lo[7]));
            *(uint4*)(smem + AS_OFF + tile_off(row, d0))       = hpk;
            *(uint4*)(smem + AS_OFF + tile_off(row, d0 + 64))  = hpk;
            *(uint4*)(smem + AS_OFF + tile_off(row, d0 + 128)) = lpk;
        }
    }

    // ---- compute qw/qh gather windows (32 vals per row each), fp32 ----
    float* qw_s = smem_f + QW_OFF / 4;   // [row][y] pitch 40
    float* qh_s = smem_f + QH_OFF / 4;   // [row][x] pitch 33
    if (warp < 8) {
        #pragma unroll 1
        for (int pass = 0; pass < 32; pass++) {
            int task = warp * 32 + pass;
            bool isW = task < 128;
            int r = isW ? task : task - 128;
            int shift = isW ? (31 - (r & 31)) : (31 - (rt * 4 + (r >> 5)));
            const float* erow = smem_f + (isW ? EWF : EHF) + (size_t)(shift + lane) * 66;
            const float* qrow = smem_f + QF + (size_t)r * 68;
            ull acc = 0;
            #pragma unroll 8
            for (int kk = 0; kk < 32; kk++) {
                ull qp = *(const ull*)(qrow + 2 * kk);   // broadcast
                ull ep = *(const ull*)(erow + 2 * kk);
                ffma2(acc, qp, ep);
            }
            float vlo, vhi; unpack2(acc, vlo, vhi);
            float v = vlo + vhi;
            if (isW) qw_s[r * 40 + lane] = v;
            else     qh_s[r * 33 + lane] = v;
        }
    }
    __syncthreads();   // staging reads done; A image + tables visible to all

    // lane decomposition for ldmatrix addressing
    const int qd = lane >> 3, r8 = lane & 7;
    const uint32_t xorv = (uint32_t)r8 << 4;
    const int mqA = qd & 1, kqA = qd >> 1;    // A: row-half, k-half
    const int jqB = qd >> 1, kqB = qd & 1;    // B: j-half, k-half
    const uint32_t a_lane = sb + AS_OFF + (uint32_t)r8 * 128;

    // epilogue lane mapping
    const int l4 = lane >> 2, l2 = (lane & 3) * 2;
    float* outb = out + ((size_t)bn << 20);

    if (warp < 8) {
        // ---- hoist qw window into registers (ct-invariant: y = nn*8 + l2) ----
        float2 wreg[8][4];                    // [mt*2+half][nn]
        #pragma unroll
        for (int rr = 0; rr < 8; rr++) {
            int r = warp_r * 64 + (rr >> 1) * 16 + (rr & 1) * 8 + l4;
            #pragma unroll
            for (int nn = 0; nn < 4; nn++)
                wreg[rr][nn] = *(const float2*)&qw_s[r * 40 + nn * 8 + l2];
        }

        for (int ct = 0; ct < 8; ct++) {
            const int buf = ct & 1;
            MBAR_WAIT(buf ? mb1 : mb0, (ct >> 1) & 1);

            const uint32_t b_lane = sb + BS_OFF + (uint32_t)buf * UNIT_BYTES
                                  + (uint32_t)r8 * 128;

            float acc[4][4][4];
            #pragma unroll
            for (int mt = 0; mt < 4; mt++)
                #pragma unroll
                for (int nn = 0; nn < 4; nn++)
                    #pragma unroll
                    for (int e = 0; e < 4; e++) acc[mt][nn][e] = 0.f;

            #pragma unroll
            for (int s = 0; s < 12; s++) {
                const int colA = s * 16 + kqA * 8;
                const uint32_t aA = ((uint32_t)(colA >> 6) * 16u) << 10;
                const uint32_t cA = (((uint32_t)(colA & 63)) << 1) ^ xorv;
                uint32_t af[4][4];
                #pragma unroll
                for (int mt = 0; mt < 4; mt++) {
                    uint32_t addr = a_lane + aA + cA
                                  + (((uint32_t)(warp_r * 8 + mt * 2 + mqA)) << 10);
                    ldsm4(af[mt][0], af[mt][1], af[mt][2], af[mt][3], addr);
                }
                const int colB = s * 16 + kqB * 8;
                const uint32_t aB = ((uint32_t)(colB >> 6) * 16u) << 10;
                const uint32_t cB = (((uint32_t)(colB & 63)) << 1) ^ xorv;
                uint32_t bf[2][4];
                #pragma unroll
                for (int ntp = 0; ntp < 2; ntp++) {
                    uint32_t addr = b_lane + aB + cB
                                  + (((uint32_t)(warp_c * 4 + ntp * 2 + jqB)) << 10);
                    ldsm4(bf[ntp][0], bf[ntp][1], bf[ntp][2], bf[ntp][3], addr);
                }
                #pragma unroll
                for (int mt = 0; mt < 4; mt++)
                    #pragma unroll
                    for (int nn = 0; nn < 4; nn++)
                        mma16816(acc[mt][nn], af[mt], &bf[nn >> 1][(nn & 1) * 2]);
            }

            // all B reads for this tile issued -> release the buffer
            if (elect_one()) MBAR_ARRIVE(buf ? mc1 : mc0);

            // epilogue overlaps other warps' MMA (no CTA barrier)
            const int xq = ct * 4 + warp_c;          // warp-uniform x index
            #pragma unroll
            for (int mt = 0; mt < 4; mt++) {
                #pragma unroll
                for (int half = 0; half < 2; half++) {
                    const int r = warp_r * 64 + mt * 16 + half * 8 + l4;
                    const float hv = qh_s[r * 33 + xq];
                    const float2* wv = wreg[mt * 2 + half];
                    float* op = outb + (size_t)(row0 + r) * 1024 + ct * 128 + warp_c * 32 + l2;
                    #pragma unroll
                    for (int nn = 0; nn < 4; nn++) {
                        float2 o;
                        o.x = acc[mt][nn][half * 2 + 0] + wv[nn].x + hv;
                        o.y = acc[mt][nn][half * 2 + 1] + wv[nn].y + hv;
                        *(float2*)(op + nn * 8) = o;
                    }
                }
            }
        }
    } else if (warp == 8) {
        // ---- producer warp: B prefetch pipeline ----
        if (elect_one()) {
            asm volatile("fence.proxy.async.shared::cta;" ::: "memory");
            MBAR_EXPECT_TX(mb0, UNIT_BYTES);
            bulk_g2s(sb + BS_OFF, g_B + (size_t)(bn * 8) * UNIT_BYTES, UNIT_BYTES, mb0);
            MBAR_EXPECT_TX(mb1, UNIT_BYTES);
            bulk_g2s(sb + BS_OFF + UNIT_BYTES, g_B + (size_t)(bn * 8 + 1) * UNIT_BYTES,
                     UNIT_BYTES, mb1);
            for (int t = 2; t < 8; t++) {
                const int b = t & 1;
                MBAR_WAIT(b ? mc1 : mc0, ((t - 2) >> 1) & 1);
                MBAR_EXPECT_TX(b ? mb1 : mb0, UNIT_BYTES);
                bulk_g2s(sb + BS_OFF + (uint32_t)b * UNIT_BYTES,
                         g_B + (size_t)(bn * 8 + t) * UNIT_BYTES, UNIT_BYTES,
                         b ? mb1 : mb0);
            }
        }
    }
}

// ----------------------------------------------------------------------------
extern "C" void kernel_launch(void* const* d_in, const int* in_sizes, int n_in,
                              void* d_out, int out_size)
{
    const float* q  = (const float*)d_in[0];
    const float* k  = (const float*)d_in[1];
    const float* ew = (const float*)d_in[2];
    const float* eh = (const float*)d_in[3];
    float* out = (float*)d_out;

    cudaFuncSetAttribute(attn_hmma_kernel, cudaFuncAttributeMaxDynamicSharedMemorySize, SMEM_SZ);

    convert_b_kernel<<<512, 256>>>(k);
    attn_hmma_kernel<<<512, 288, SMEM_SZ>>>(q, ew, eh, out);
}

// round 9
// speedup vs baseline: 2.0428x; 1.0917x over previous
#include <cuda_runtime.h>
#include <cuda_bf16.h>
#include <cstdint>

// ============================================================================
// RelativeAttention (sm_103, TF32 HMMA path, warp-desynced pipeline)
//
// out[bn,i=(h,w),j=(x,y)] = dot(q_i,k_j) + QW[bn,i, y-w+31] + QH[bn,i, x-h+31]
//
// K1 (convert_b): k -> tf32-rounded f32, chunk-XOR-swizzled K-major images
// K2 (attn_hmma): 288 thr = 8 worker warps + 1 producer warp.
//   - stage q (linear, A region) + ew/eh (B region); exact fp32 qw/qh windows
//   - A image built in place: q -> regs -> swizzled tf32
//   - 8x 128x128 tiles, K=64 in 8 k8-steps of mma.m16n8k8.tf32
//   - B double-buffered via producer-warp cp.async.bulk + consumed mbarriers
//   - epilogue: reg-hoisted qw window + smem qh, STG.64
// ============================================================================

#define BNB 64
#define LQ  1024
#define DD  64
#define UNIT_BYTES 32768          // 128 rows x 64 f32 (tf32)

__device__ __align__(1024) unsigned char g_B[(size_t)512 * UNIT_BYTES];

typedef unsigned long long ull;

// ---------------- helpers ----------------
__device__ __forceinline__ void ffma2(ull& acc, ull a, ull b) {
    asm("fma.rn.f32x2 %0, %1, %2, %0;" : "+l"(acc) : "l"(a), "l"(b));
}
__device__ __forceinline__ void unpack2(ull v, float& lo, float& hi) {
    asm("mov.b64 {%0, %1}, %2;" : "=f"(lo), "=f"(hi) : "l"(v));
}
__device__ __forceinline__ float tf32r(float x) {
    float r; asm("cvt.rna.tf32.f32 %0, %1;" : "=f"(r) : "f"(x)); return r;
}
__device__ __forceinline__ uint32_t smem_u32(const void* p) {
    uint32_t a;
    asm("{ .reg .u64 t; cvta.to.shared.u64 t, %1; cvt.u32.u64 %0, t; }" : "=r"(a) : "l"(p));
    return a;
}
__device__ __forceinline__ uint32_t elect_one() {
    uint32_t p;
    asm volatile("{ .reg .pred p; elect.sync _|p, 0xFFFFFFFF; selp.b32 %0, 1, 0, p; }" : "=r"(p));
    return p;
}

#define MBAR_INIT(a, c) \
    asm volatile("mbarrier.init.shared.b64 [%0], %1;" :: "r"(a), "r"(c) : "memory")
#define MBAR_EXPECT_TX(a, b) \
    asm volatile("mbarrier.arrive.expect_tx.shared.b64 _, [%0], %1;" :: "r"(a), "r"(b) : "memory")
#define MBAR_ARRIVE(a) \
    asm volatile("mbarrier.arrive.shared.b64 _, [%0];" :: "r"(a) : "memory")
#define MBAR_WAIT(a, ph) do {                                                   \
    asm volatile("{\n\t.reg .pred P1;\n\t"                                      \
        "WL%=:\n\t"                                                             \
        "mbarrier.try_wait.parity.acquire.cta.shared::cta.b64 P1, [%0], %1, 0x989680;\n\t" \
        "@P1 bra.uni WD%=;\n\t bra.uni WL%=;\n\tWD%=:\n\t}"                      \
        :: "r"(a), "r"(ph) : "memory");                                          \
} while (0)

__device__ __forceinline__ void bulk_g2s(uint32_t dst, const void* src, uint32_t bytes, uint32_t mbar) {
    uint64_t gsrc = (uint64_t)__cvta_generic_to_global(src);
    asm volatile("cp.async.bulk.shared::cta.global.mbarrier::complete_tx::bytes [%0], [%1], %2, [%3];"
                 :: "r"(dst), "l"(gsrc), "r"(bytes), "r"(mbar) : "memory");
}

__device__ __forceinline__ void ldsm4(uint32_t& r0, uint32_t& r1, uint32_t& r2, uint32_t& r3,
                                      uint32_t addr) {
    asm volatile("ldmatrix.sync.aligned.m8n8.x4.shared.b16 {%0,%1,%2,%3}, [%4];"
                 : "=r"(r0), "=r"(r1), "=r"(r2), "=r"(r3) : "r"(addr));
}
__device__ __forceinline__ void mma_tf32(float* c, const uint32_t* a, const uint32_t* b) {
    asm volatile("mma.sync.aligned.m16n8k8.row.col.f32.tf32.tf32.f32 "
                 "{%0,%1,%2,%3}, {%4,%5,%6,%7}, {%8,%9}, {%0,%1,%2,%3};"
                 : "+f"(c[0]), "+f"(c[1]), "+f"(c[2]), "+f"(c[3])
                 : "r"(a[0]), "r"(a[1]), "r"(a[2]), "r"(a[3]), "r"(b[0]), "r"(b[1]));
}

// image layout: 128 rows x 256B; 16B chunk c at row r lands at chunk (c ^ (r&7))
__device__ __forceinline__ uint32_t img_off(int row, int chunk) {
    return (uint32_t)row * 256u + (uint32_t)((chunk ^ (row & 7)) * 16);
}

// ----------------------------------------------------------------------------
// Kernel 1: convert k -> tf32 swizzled K-major images
// ----------------------------------------------------------------------------
__global__ __launch_bounds__(256) void convert_b_kernel(const float* __restrict__ k)
{
    int unit = blockIdx.x;
    const float* base = k + (size_t)unit * 128 * DD;
    unsigned char* dst = g_B + (size_t)unit * UNIT_BYTES;
    int tid = threadIdx.x;

    #pragma unroll
    for (int c = 0; c < 4; c++) {
        int chunk = tid + c * 256;          // 0..1023
        int row = chunk >> 3;
        int d0  = (chunk & 7) * 8;
        float4 v0 = *(const float4*)&base[row * DD + d0];
        float4 v1 = *(const float4*)&base[row * DD + d0 + 4];
        float4 o0 = make_float4(tf32r(v0.x), tf32r(v0.y), tf32r(v0.z), tf32r(v0.w));
        float4 o1 = make_float4(tf32r(v1.x), tf32r(v1.y), tf32r(v1.z), tf32r(v1.w));
        *(float4*)(dst + img_off(row, (d0 >> 2)))     = o0;
        *(float4*)(dst + img_off(row, (d0 >> 2) + 1)) = o1;
    }
}

// ----------------------------------------------------------------------------
// Kernel 2: fused tables + A-convert + TF32 HMMA GEMM + epilogue
// ----------------------------------------------------------------------------
// byte offsets
#define AS_OFF   0                     // A image 32KB (pre-GEMM: q fp32 linear)
#define BS_OFF   32768                 // two B buffers 2x32KB (pre-GEMM: ew/eh)
#define QW_OFF   98304                 // 128 x pitch40 f32 = 20480
#define QH_OFF   118784                // 128 x pitch33 f32 = 16896
#define CTRL_OFF 135680
#define SMEM_SZ  135744
// float-index offsets for ew/eh staging inside the B-buffer region
#define EWF  (BS_OFF / 4)              // ew: 63 rows x pitch66 (float2 stores)
#define EHF  (EWF + 4160)              // eh: 63 rows x pitch66

__global__ __launch_bounds__(288, 1) void attn_hmma_kernel(
    const float* __restrict__ q, const float* __restrict__ ew,
    const float* __restrict__ eh, float* __restrict__ out)
{
    extern __shared__ unsigned char smem[];
    float* smem_f = (float*)smem;
    const uint32_t sb = smem_u32(smem);

    const int bn = blockIdx.x >> 3;
    const int rt = blockIdx.x & 7;
    const int row0 = rt * 128;
    const int n_head = bn & 7;
    const int tid = threadIdx.x, lane = tid & 31, warp = tid >> 5;
    const int warp_r = warp >> 2;     // workers: 0..1 -> 64-row half
    const int warp_c = warp & 3;      // workers: 0..3 -> 32-col strip

    const uint32_t mb0 = sb + CTRL_OFF,      mb1 = mb0 + 8;   // B-full (count 1)
    const uint32_t mc0 = mb0 + 16,           mc1 = mb0 + 24;  // B-consumed (count 8)
    if (tid == 0) {
        MBAR_INIT(mb0, 1); MBAR_INIT(mb1, 1);
        MBAR_INIT(mc0, 8); MBAR_INIT(mc1, 8);
    }

    // ---- phase A: stage q (linear, pitch 64, into A region) + ew/eh ----
    if (tid < 256) {
        const float* ewb = ew + (size_t)n_head * 63 * DD;
        const float* ehb = eh + (size_t)n_head * 63 * DD;
        for (int c = tid; c < 1008; c += 256) {          // 63 rows x 16 float4
            int row = c >> 4, d0 = (c & 15) * 4;
            float4 vw = *(const float4*)&ewb[row * DD + d0];
            float4 vh = *(const float4*)&ehb[row * DD + d0];
            float* dw = &smem_f[EWF + row * 66 + d0];
            float* dh = &smem_f[EHF + row * 66 + d0];
            *(float2*)(dw + 0) = make_float2(vw.x, vw.y);
            *(float2*)(dw + 2) = make_float2(vw.z, vw.w);
            *(float2*)(dh + 0) = make_float2(vh.x, vh.y);
            *(float2*)(dh + 2) = make_float2(vh.z, vh.w);
        }
        const float* qb = q + ((size_t)bn * LQ + row0) * DD;
        #pragma unroll
        for (int it = 0; it < 8; it++) {                 // 128 rows x 16 float4
            int c = tid + it * 256;
            int row = c >> 4, d0 = (c & 15) * 4;
            *(float4*)&smem_f[row * 64 + d0] = *(const float4*)&qb[(size_t)row * DD + d0];
        }
    }
    __syncthreads();

    // ---- phase B: exact fp32 qw/qh windows + read q into regs ----
    float* qw_s = smem_f + QW_OFF / 4;   // [row][y] pitch 40
    float* qh_s = smem_f + QH_OFF / 4;   // [row][x] pitch 33
    if (warp < 8) {
        #pragma unroll 1
        for (int pass = 0; pass < 32; pass++) {
            int task = warp * 32 + pass;
            bool isW = task < 128;
            int r = isW ? task : task - 128;
            int shift = isW ? (31 - (r & 31)) : (31 - (rt * 4 + (r >> 5)));
            const float* erow = smem_f + (isW ? EWF : EHF) + (size_t)(shift + lane) * 66;
            const float* qrow = smem_f + (size_t)r * 64;
            ull acc = 0;
            #pragma unroll 8
            for (int kk = 0; kk < 32; kk++) {
                ull qp = *(const ull*)(qrow + 2 * kk);   // broadcast
                ull ep = *(const ull*)(erow + 2 * kk);
                ffma2(acc, qp, ep);
            }
            float vlo, vhi; unpack2(acc, vlo, vhi);
            float v = vlo + vhi;
            if (isW) qw_s[r * 40 + lane] = v;
            else     qh_s[r * 33 + lane] = v;
        }
    }
    // read q chunks that this thread will rewrite swizzled (reads only here)
    float qreg[4][8];
    if (tid < 256) {
        #pragma unroll
        for (int c = 0; c < 4; c++) {
            int chunk = tid + c * 256;
            int row = chunk >> 3, d0 = (chunk & 7) * 8;
            float4 v0 = *(const float4*)&smem_f[row * 64 + d0];
            float4 v1 = *(const float4*)&smem_f[row * 64 + d0 + 4];
            qreg[c][0] = v0.x; qreg[c][1] = v0.y; qreg[c][2] = v0.z; qreg[c][3] = v0.w;
            qreg[c][4] = v1.x; qreg[c][5] = v1.y; qreg[c][6] = v1.z; qreg[c][7] = v1.w;
        }
    }
    __syncthreads();   // all q reads done; tables written

    // ---- phase C: write swizzled tf32 A image in place ----
    if (tid < 256) {
        #pragma unroll
        for (int c = 0; c < 4; c++) {
            int chunk = tid + c * 256;
            int row = chunk >> 3, d0 = (chunk & 7) * 8;
            float4 o0 = make_float4(tf32r(qreg[c][0]), tf32r(qreg[c][1]),
                                    tf32r(qreg[c][2]), tf32r(qreg[c][3]));
            float4 o1 = make_float4(tf32r(qreg[c][4]), tf32r(qreg[c][5]),
                                    tf32r(qreg[c][6]), tf32r(qreg[c][7]));
            *(float4*)(smem + AS_OFF + img_off(row, (d0 >> 2)))     = o0;
            *(float4*)(smem + AS_OFF + img_off(row, (d0 >> 2) + 1)) = o1;
        }
    }
    __syncthreads();   // A image ready; ew/eh region free for B loads

    // lane decomposition for ldmatrix addressing (f32 8x4 blocks as b16 m8n8)
    const int r8 = lane & 7;
    const int ma = (lane >> 3) & 1, ka = lane >> 4;   // A: row-half, chunk-half
    const int gb = lane >> 4,       cb = (lane >> 3) & 1; // B: n-group, chunk-half
    const uint32_t a_base = sb + AS_OFF + (uint32_t)(warp_r * 64 + ma * 8 + r8) * 256;

    // epilogue lane mapping
    const int l4 = lane >> 2, l2 = (lane & 3) * 2;
    float* outb = out + ((size_t)bn << 20);

    if (warp < 8) {
        // hoist qw window into registers (ct-invariant: y = nn*8 + l2)
        float2 wreg[8][4];                    // [mt*2+half][nn]
        #pragma unroll
        for (int rr = 0; rr < 8; rr++) {
            int r = warp_r * 64 + (rr >> 1) * 16 + (rr & 1) * 8 + l4;
            #pragma unroll
            for (int nn = 0; nn < 4; nn++)
                wreg[rr][nn] = *(const float2*)&qw_s[r * 40 + nn * 8 + l2];
        }

        for (int ct = 0; ct < 8; ct++) {
            const int buf = ct & 1;
            MBAR_WAIT(buf ? mb1 : mb0, (ct >> 1) & 1);

            const uint32_t b_base = sb + BS_OFF + (uint32_t)buf * UNIT_BYTES
                                  + (uint32_t)(warp_c * 32 + gb * 8 + r8) * 256;

            float acc[4][4][4];
            #pragma unroll
            for (int mt = 0; mt < 4; mt++)
                #pragma unroll
                for (int nn = 0; nn < 4; nn++)
                    #pragma unroll
                    for (int e = 0; e < 4; e++) acc[mt][nn][e] = 0.f;

            #pragma unroll
            for (int s = 0; s < 8; s++) {
                uint32_t af[4][4];
                const uint32_t ca = (uint32_t)(((2 * s + ka) ^ r8) * 16);
                #pragma unroll
                for (int mt = 0; mt < 4; mt++)
                    ldsm4(af[mt][0], af[mt][1], af[mt][2], af[mt][3],
                          a_base + (uint32_t)(mt * 16 * 256) + ca);
                uint32_t bf[2][4];
                const uint32_t cbb = (uint32_t)(((2 * s + cb) ^ r8) * 16);
                #pragma unroll
                for (int np = 0; np < 2; np++)
                    ldsm4(bf[np][0], bf[np][1], bf[np][2], bf[np][3],
                          b_base + (uint32_t)(np * 16 * 256) + cbb);
                #pragma unroll
                for (int mt = 0; mt < 4; mt++)
                    #pragma unroll
                    for (int nn = 0; nn < 4; nn++)
                        mma_tf32(acc[mt][nn], af[mt], &bf[nn >> 1][(nn & 1) * 2]);
            }

            // all B reads for this tile issued -> release the buffer
            if (elect_one()) MBAR_ARRIVE(buf ? mc1 : mc0);

            // epilogue overlaps other warps' MMA (no CTA barrier)
            const int xq = ct * 4 + warp_c;          // warp-uniform x index
            #pragma unroll
            for (int mt = 0; mt < 4; mt++) {
                #pragma unroll
                for (int half = 0; half < 2; half++) {
                    const int r = warp_r * 64 + mt * 16 + half * 8 + l4;
                    const float hv = qh_s[r * 33 + xq];
                    const float2* wv = wreg[mt * 2 + half];
                    float* op = outb + (size_t)(row0 + r) * 1024 + ct * 128 + warp_c * 32 + l2;
                    #pragma unroll
                    for (int nn = 0; nn < 4; nn++) {
                        float2 o;
                        o.x = acc[mt][nn][half * 2 + 0] + wv[nn].x + hv;
                        o.y = acc[mt][nn][half * 2 + 1] + wv[nn].y + hv;
                        *(float2*)(op + nn * 8) = o;
                    }
                }
            }
        }
    } else if (warp == 8) {
        // ---- producer warp: B prefetch pipeline ----
        if (elect_one()) {
            asm volatile("fence.proxy.async.shared::cta;" ::: "memory");
            MBAR_EXPECT_TX(mb0, UNIT_BYTES);
            bulk_g2s(sb + BS_OFF, g_B + (size_t)(bn * 8) * UNIT_BYTES, UNIT_BYTES, mb0);
            MBAR_EXPECT_TX(mb1, UNIT_BYTES);
            bulk_g2s(sb + BS_OFF + UNIT_BYTES, g_B + (size_t)(bn * 8 + 1) * UNIT_BYTES,
                     UNIT_BYTES, mb1);
            for (int t = 2; t < 8; t++) {
                const int b = t & 1;
                MBAR_WAIT(b ? mc1 : mc0, ((t - 2) >> 1) & 1);
                MBAR_EXPECT_TX(b ? mb1 : mb0, UNIT_BYTES);
                bulk_g2s(sb + BS_OFF + (uint32_t)b * UNIT_BYTES,
                         g_B + (size_t)(bn * 8 + t) * UNIT_BYTES, UNIT_BYTES,
                         b ? mb1 : mb0);
            }
        }
    }
}

// ----------------------------------------------------------------------------
extern "C" void kernel_launch(void* const* d_in, const int* in_sizes, int n_in,
                              void* d_out, int out_size)
{
    const float* q  = (const float*)d_in[0];
    const float* k  = (const float*)d_in[1];
    const float* ew = (const float*)d_in[2];
    const float* eh = (const float*)d_in[3];
    float* out = (float*)d_out;

    cudaFuncSetAttribute(attn_hmma_kernel, cudaFuncAttributeMaxDynamicSharedMemorySize, SMEM_SZ);

    convert_b_kernel<<<512, 256>>>(k);
    attn_hmma_kernel<<<512, 288, SMEM_SZ>>>(q, ew, eh, out);
}